// round 3
// baseline (speedup 1.0000x reference)
#include <cuda_runtime.h>

// Problem constants
static const int FR = 8 * 64 * 64 * 64;  // one frame of h/c: B*H*W*F = 2097152 floats

// Scratch (device globals -- no allocation allowed)
__device__ float g_hist0[10ull * 2097152];  // layer0 h history [t][b][h][w][f]
__device__ float g_hist1[10ull * 2097152];  // layer1 h history
__device__ float g_c0[2097152];             // layer0 cell state
__device__ float g_c1[2097152];             // layer1 cell state

// ---------- packed f32x2 helpers (Blackwell FFMA2) ----------
__device__ __forceinline__ unsigned long long pack2(float a) {
    unsigned long long r;
    asm("mov.b64 %0, {%1, %1};" : "=l"(r) : "f"(a));
    return r;
}
__device__ __forceinline__ void fma2(unsigned long long& d, unsigned long long a, unsigned long long b) {
    asm("fma.rn.f32x2 %0, %1, %2, %0;" : "+l"(d) : "l"(a), "l"(b));
}
__device__ __forceinline__ float2 unpk(unsigned long long v) {
    float2 f;
    asm("mov.b64 {%0, %1}, %2;" : "=f"(f.x), "=f"(f.y) : "l"(v));
    return f;
}
__device__ __forceinline__ float hsig(float x) { return __saturatef(fmaf(0.2f, x, 0.5f)); }

// Load a [3 rows][66 cols][64 ch] halo tile, transposed to smem [dy][cin][66]
// frame: NHWC image base for this batch element ([64][64][64] floats)
__device__ __forceinline__ void load_tile64(float* __restrict__ s,
                                            const float* __restrict__ frame,
                                            int h, int tid)
{
    for (int idx = tid; idx < 3 * 66 * 16; idx += 256) {
        int c4 = idx & 15;
        int colr = idx >> 4;
        int col = colr % 66;
        int dy = colr / 66;
        int row = h + dy - 1;
        int win = col - 1;
        float4 v = make_float4(0.f, 0.f, 0.f, 0.f);
        if ((unsigned)row < 64u && (unsigned)win < 64u)
            v = *(const float4*)&frame[(row * 64 + win) * 64 + c4 * 4];
        int base = (dy * 64 + c4 * 4) * 66 + col;
        s[base]       = v.x;
        s[base + 66]  = v.y;
        s[base + 132] = v.z;
        s[base + 198] = v.w;
    }
}

// One 3x3 conv contribution with CIN=64: acc += conv(sIn, gw)
// sIn: smem [3][64][66]; gw: global weights [9*64][256] (HWIO flattened k-major)
__device__ __forceinline__ void conv_part64(unsigned long long acc[4][4][2],
                                            const float* __restrict__ sIn,
                                            const float* __restrict__ gw,
                                            float* __restrict__ sW,
                                            int tid, int w0, int n0)
{
    for (int tap = 0; tap < 9; ++tap) {
        const float* sbase = sIn + (tap / 3) * (64 * 66) + (tap % 3) + w0;
        const float4* wsrc = (const float4*)(gw + tap * 64 * 256);
        for (int ch = 0; ch < 4; ++ch) {
            __syncthreads();
            float4* dst = (float4*)sW;
#pragma unroll
            for (int i = 0; i < 4; ++i)
                dst[tid + i * 256] = wsrc[ch * 1024 + tid + i * 256];
            __syncthreads();
#pragma unroll
            for (int kk = 0; kk < 16; ++kk) {
                const float* a = sbase + (ch * 16 + kk) * 66;
                unsigned long long aa0 = pack2(a[0]);
                unsigned long long aa1 = pack2(a[1]);
                unsigned long long aa2 = pack2(a[2]);
                unsigned long long aa3 = pack2(a[3]);
                const float* brow = sW + kk * 256 + n0;
#pragma unroll
                for (int g = 0; g < 4; ++g) {
                    ulonglong2 bb = *(const ulonglong2*)(brow + g * 64);
                    fma2(acc[0][g][0], aa0, bb.x); fma2(acc[0][g][1], aa0, bb.y);
                    fma2(acc[1][g][0], aa1, bb.x); fma2(acc[1][g][1], aa1, bb.y);
                    fma2(acc[2][g][0], aa2, bb.x); fma2(acc[2][g][1], aa2, bb.y);
                    fma2(acc[3][g][0], aa3, bb.x); fma2(acc[3][g][1], aa3, bb.y);
                }
            }
        }
    }
}

// Fused ConvLSTM step: gates = b + conv(x_t, Wx) + conv(h_prev, Wh);
// c = hs(f)*c + hs(i)*tanh(g); h = hs(o)*tanh(c).
// Block = one (b,h) row, all 64 w x 256 gate channels.
template <int CIN_X, bool HAS_PREV>
__global__ __launch_bounds__(256)
void step_kernel(const float* __restrict__ xin, long long xin_bstride,
                 const float* __restrict__ hprev,
                 const float* __restrict__ Wx,
                 const float* __restrict__ Wh,
                 const float* __restrict__ bias,
                 float* __restrict__ cbuf,
                 float* __restrict__ hout)
{
    extern __shared__ float smem[];
    // Pad each region to a multiple of 4 floats so every base is 16B-aligned
    // (float4 / LDS.128 / STS.128 would otherwise trap: misaligned address).
    constexpr int SXSZ = ((3 * 66 * CIN_X) + 3) & ~3;                // 198 -> 200
    constexpr int SHSZ = HAS_PREV ? (((3 * 66 * 64) + 3) & ~3) : 0;  // 12672 (already aligned)
    float* sX = smem;
    float* sH = smem + SXSZ;
    float* sW = smem + SXSZ + SHSZ;

    const int tid = threadIdx.x;
    const int bh = blockIdx.x;          // b*64 + h
    const int b = bh >> 6, h = bh & 63;
    const int tn = tid & 15, tw = tid >> 4;
    const int w0 = tw * 4, n0 = tn * 4;

    const float* xframe = xin + (long long)b * xin_bstride;
    if constexpr (CIN_X == 1) {
        for (int idx = tid; idx < 3 * 66; idx += 256) {
            int dy = idx / 66, col = idx - dy * 66;
            int row = h + dy - 1, win = col - 1;
            float v = 0.f;
            if ((unsigned)row < 64u && (unsigned)win < 64u) v = xframe[row * 64 + win];
            sX[idx] = v;
        }
    } else {
        load_tile64(sX, xframe, h, tid);
    }
    if constexpr (HAS_PREV) {
        load_tile64(sH, hprev + (long long)b * (64 * 64 * 64), h, tid);
    }

    unsigned long long acc[4][4][2];
#pragma unroll
    for (int i = 0; i < 4; i++)
#pragma unroll
        for (int g = 0; g < 4; g++) { acc[i][g][0] = 0ull; acc[i][g][1] = 0ull; }

    if constexpr (CIN_X == 1) {
        __syncthreads();
        for (int i = tid; i < 576; i += 256) ((float4*)sW)[i] = ((const float4*)Wx)[i];
        __syncthreads();
        for (int tap = 0; tap < 9; ++tap) {
            const float* a = sX + (tap / 3) * 66 + (tap % 3) + w0;
            unsigned long long aa0 = pack2(a[0]);
            unsigned long long aa1 = pack2(a[1]);
            unsigned long long aa2 = pack2(a[2]);
            unsigned long long aa3 = pack2(a[3]);
            const float* brow = sW + tap * 256 + n0;
#pragma unroll
            for (int g = 0; g < 4; ++g) {
                ulonglong2 bb = *(const ulonglong2*)(brow + g * 64);
                fma2(acc[0][g][0], aa0, bb.x); fma2(acc[0][g][1], aa0, bb.y);
                fma2(acc[1][g][0], aa1, bb.x); fma2(acc[1][g][1], aa1, bb.y);
                fma2(acc[2][g][0], aa2, bb.x); fma2(acc[2][g][1], aa2, bb.y);
                fma2(acc[3][g][0], aa3, bb.x); fma2(acc[3][g][1], aa3, bb.y);
            }
        }
    } else {
        conv_part64(acc, sX, Wx, sW, tid, w0, n0);
    }
    if constexpr (HAS_PREV) {
        conv_part64(acc, sH, Wh, sW, tid, w0, n0);
    }

    // ---------- fused epilogue: bias + activations + state update ----------
    float bg[4][4];
#pragma unroll
    for (int g = 0; g < 4; ++g) {
        float4 t = *(const float4*)(bias + g * 64 + n0);
        bg[g][0] = t.x; bg[g][1] = t.y; bg[g][2] = t.z; bg[g][3] = t.w;
    }
    const long long obase = ((long long)bh * 64 + w0) * 64 + n0;
#pragma unroll
    for (int i = 0; i < 4; i++) {
        long long off = obase + (long long)i * 64;
        float cp[4] = {0.f, 0.f, 0.f, 0.f};
        if constexpr (HAS_PREV) {
            float4 t = *(const float4*)&cbuf[off];
            cp[0] = t.x; cp[1] = t.y; cp[2] = t.z; cp[3] = t.w;
        }
        float gv[4][4];
#pragma unroll
        for (int g = 0; g < 4; ++g) {
            float2 p0 = unpk(acc[i][g][0]);
            float2 p1 = unpk(acc[i][g][1]);
            gv[g][0] = p0.x + bg[g][0];
            gv[g][1] = p0.y + bg[g][1];
            gv[g][2] = p1.x + bg[g][2];
            gv[g][3] = p1.y + bg[g][3];
        }
        float cn[4], hn[4];
#pragma unroll
        for (int j = 0; j < 4; j++) {
            float iv = hsig(gv[0][j]);
            float fv = hsig(gv[1][j]);
            float gg = tanhf(gv[2][j]);
            float ov = hsig(gv[3][j]);
            float c = fv * cp[j] + iv * gg;
            cn[j] = c;
            hn[j] = ov * tanhf(c);
        }
        *(float4*)&cbuf[off] = make_float4(cn[0], cn[1], cn[2], cn[3]);
        *(float4*)&hout[off] = make_float4(hn[0], hn[1], hn[2], hn[3]);
    }
}

extern "C" void kernel_launch(void* const* d_in, const int* in_sizes, int n_in,
                              void* d_out, int out_size)
{
    const float* x   = (const float*)d_in[0];  // [8,10,64,64,1]
    const float* Wx0 = (const float*)d_in[1];  // [3,3,1,256]
    const float* Wh0 = (const float*)d_in[2];  // [3,3,64,256]
    const float* b0  = (const float*)d_in[3];  // [256]
    const float* Wx1 = (const float*)d_in[4];  // [3,3,64,256]
    const float* Wh1 = (const float*)d_in[5];  // [3,3,64,256]
    const float* b1  = (const float*)d_in[6];  // [256]
    float* out = (float*)d_out;                // [2,2,8,64,64,64]

    float *hist0, *hist1, *c0, *c1;
    cudaGetSymbolAddress((void**)&hist0, g_hist0);
    cudaGetSymbolAddress((void**)&hist1, g_hist1);
    cudaGetSymbolAddress((void**)&c0, g_c0);
    cudaGetSymbolAddress((void**)&c1, g_c1);

    const int SM_1N  = (200 + 4096) * 4;
    const int SM_1P  = (200 + 12672 + 4096) * 4;
    const int SM_64N = (12672 + 4096) * 4;
    const int SM_64P = (2 * 12672 + 4096) * 4;
    cudaFuncSetAttribute(step_kernel<1, false>,  cudaFuncAttributeMaxDynamicSharedMemorySize, SM_1N);
    cudaFuncSetAttribute(step_kernel<1, true>,   cudaFuncAttributeMaxDynamicSharedMemorySize, SM_1P);
    cudaFuncSetAttribute(step_kernel<64, false>, cudaFuncAttributeMaxDynamicSharedMemorySize, SM_64N);
    cudaFuncSetAttribute(step_kernel<64, true>,  cudaFuncAttributeMaxDynamicSharedMemorySize, SM_64P);

    dim3 grid(512), block(256);

    // Layer 0: x frame t at x + t*4096, batch stride T*H*W = 40960
    step_kernel<1, false><<<grid, block, SM_1N>>>(x, 40960LL, nullptr,
                                                  Wx0, Wh0, b0, c0, hist0);
    for (int t = 1; t < 10; ++t)
        step_kernel<1, true><<<grid, block, SM_1P>>>(x + (size_t)t * 4096, 40960LL,
                                                     hist0 + (size_t)(t - 1) * FR,
                                                     Wx0, Wh0, b0, c0,
                                                     hist0 + (size_t)t * FR);

    // Layer 1: input is hist0 frames, batch stride H*W*F = 262144
    step_kernel<64, false><<<grid, block, SM_64N>>>(hist0, 262144LL, nullptr,
                                                    Wx1, Wh1, b1, c1, hist1);
    for (int t = 1; t < 10; ++t)
        step_kernel<64, true><<<grid, block, SM_64P>>>(hist0 + (size_t)t * FR, 262144LL,
                                                       hist1 + (size_t)(t - 1) * FR,
                                                       Wx1, Wh1, b1, c1,
                                                       hist1 + (size_t)t * FR);

    // Pack output: [ [h0,c0], [h1,c1] ]
    cudaMemcpyAsync(out,                 hist0 + 9ull * FR, (size_t)FR * 4, cudaMemcpyDeviceToDevice);
    cudaMemcpyAsync(out + (size_t)FR,    c0,                (size_t)FR * 4, cudaMemcpyDeviceToDevice);
    cudaMemcpyAsync(out + 2ull * FR,     hist1 + 9ull * FR, (size_t)FR * 4, cudaMemcpyDeviceToDevice);
    cudaMemcpyAsync(out + 3ull * FR,     c1,                (size_t)FR * 4, cudaMemcpyDeviceToDevice);
}

// round 4
// speedup vs baseline: 1.0009x; 1.0009x over previous
#include <cuda_runtime.h>

// Problem constants
static const int FR = 8 * 64 * 64 * 64;  // one frame of h/c: B*H*W*F = 2097152 floats

// Scratch (device globals -- no allocation allowed)
__device__ float g_hist0[10ull * 2097152];  // layer0 h history [t][b][h][w][f]
__device__ float g_hist1[10ull * 2097152];  // layer1 h history
__device__ float g_c0[2097152];             // layer0 cell state
__device__ float g_c1[2097152];             // layer1 cell state

// ---------- packed f32x2 helpers (Blackwell FFMA2) ----------
__device__ __forceinline__ unsigned long long pack2(float a) {
    unsigned long long r;
    asm("mov.b64 %0, {%1, %1};" : "=l"(r) : "f"(a));
    return r;
}
__device__ __forceinline__ void fma2(unsigned long long& d, unsigned long long a, unsigned long long b) {
    asm("fma.rn.f32x2 %0, %1, %2, %0;" : "+l"(d) : "l"(a), "l"(b));
}
__device__ __forceinline__ float2 unpk(unsigned long long v) {
    float2 f;
    asm("mov.b64 {%0, %1}, %2;" : "=f"(f.x), "=f"(f.y) : "l"(v));
    return f;
}
__device__ __forceinline__ float hsig(float x) { return __saturatef(fmaf(0.2f, x, 0.5f)); }

// Load a [3 rows][66 cols][64 ch] halo tile, transposed to smem [dy][cin][66]
// frame: NHWC image base for this batch element ([64][64][64] floats)
__device__ __forceinline__ void load_tile64(float* __restrict__ s,
                                            const float* __restrict__ frame,
                                            int h, int tid)
{
    for (int idx = tid; idx < 3 * 66 * 16; idx += 256) {
        int c4 = idx & 15;
        int colr = idx >> 4;
        int col = colr % 66;
        int dy = colr / 66;
        int row = h + dy - 1;
        int win = col - 1;
        float4 v = make_float4(0.f, 0.f, 0.f, 0.f);
        if ((unsigned)row < 64u && (unsigned)win < 64u)
            v = *(const float4*)&frame[(row * 64 + win) * 64 + c4 * 4];
        int base = (dy * 64 + c4 * 4) * 66 + col;
        s[base]       = v.x;
        s[base + 66]  = v.y;
        s[base + 132] = v.z;
        s[base + 198] = v.w;
    }
}

// One 3x3 conv contribution with CIN=64: acc += conv(sIn, gw)
// sIn: smem [3][64][66]; gw: global weights [9*64][256] (HWIO flattened k-major)
__device__ __forceinline__ void conv_part64(unsigned long long acc[4][4][2],
                                            const float* __restrict__ sIn,
                                            const float* __restrict__ gw,
                                            float* __restrict__ sW,
                                            int tid, int w0, int n0)
{
    for (int tap = 0; tap < 9; ++tap) {
        const float* sbase = sIn + (tap / 3) * (64 * 66) + (tap % 3) + w0;
        const float4* wsrc = (const float4*)(gw + tap * 64 * 256);
        for (int ch = 0; ch < 4; ++ch) {
            __syncthreads();
            float4* dst = (float4*)sW;
#pragma unroll
            for (int i = 0; i < 4; ++i)
                dst[tid + i * 256] = wsrc[ch * 1024 + tid + i * 256];
            __syncthreads();
#pragma unroll
            for (int kk = 0; kk < 16; ++kk) {
                const float* a = sbase + (ch * 16 + kk) * 66;
                unsigned long long aa0 = pack2(a[0]);
                unsigned long long aa1 = pack2(a[1]);
                unsigned long long aa2 = pack2(a[2]);
                unsigned long long aa3 = pack2(a[3]);
                const float* brow = sW + kk * 256 + n0;
#pragma unroll
                for (int g = 0; g < 4; ++g) {
                    ulonglong2 bb = *(const ulonglong2*)(brow + g * 64);
                    fma2(acc[0][g][0], aa0, bb.x); fma2(acc[0][g][1], aa0, bb.y);
                    fma2(acc[1][g][0], aa1, bb.x); fma2(acc[1][g][1], aa1, bb.y);
                    fma2(acc[2][g][0], aa2, bb.x); fma2(acc[2][g][1], aa2, bb.y);
                    fma2(acc[3][g][0], aa3, bb.x); fma2(acc[3][g][1], aa3, bb.y);
                }
            }
        }
    }
}

// Fused ConvLSTM step: gates = b + conv(x_t, Wx) + conv(h_prev, Wh);
// c = hs(f)*c + hs(i)*tanh(g); h = hs(o)*tanh(c).
// Block = one (b,h) row, all 64 w x 256 gate channels.
template <int CIN_X, bool HAS_PREV>
__global__ __launch_bounds__(256)
void step_kernel(const float* __restrict__ xin, long long xin_bstride,
                 const float* __restrict__ hprev,
                 const float* __restrict__ Wx,
                 const float* __restrict__ Wh,
                 const float* __restrict__ bias,
                 float* __restrict__ cbuf,
                 float* __restrict__ hout)
{
    extern __shared__ float smem[];
    // Pad each region to a multiple of 4 floats so every base is 16B-aligned
    // (float4 / LDS.128 / STS.128 would otherwise trap: misaligned address).
    constexpr int SXSZ = ((3 * 66 * CIN_X) + 3) & ~3;                // 198 -> 200
    constexpr int SHSZ = HAS_PREV ? (((3 * 66 * 64) + 3) & ~3) : 0;  // 12672 (already aligned)
    float* sX = smem;
    float* sH = smem + SXSZ;
    float* sW = smem + SXSZ + SHSZ;

    const int tid = threadIdx.x;
    const int bh = blockIdx.x;          // b*64 + h
    const int b = bh >> 6, h = bh & 63;
    const int tn = tid & 15, tw = tid >> 4;
    const int w0 = tw * 4, n0 = tn * 4;

    const float* xframe = xin + (long long)b * xin_bstride;
    if constexpr (CIN_X == 1) {
        for (int idx = tid; idx < 3 * 66; idx += 256) {
            int dy = idx / 66, col = idx - dy * 66;
            int row = h + dy - 1, win = col - 1;
            float v = 0.f;
            if ((unsigned)row < 64u && (unsigned)win < 64u) v = xframe[row * 64 + win];
            sX[idx] = v;
        }
    } else {
        load_tile64(sX, xframe, h, tid);
    }
    if constexpr (HAS_PREV) {
        load_tile64(sH, hprev + (long long)b * (64 * 64 * 64), h, tid);
    }

    unsigned long long acc[4][4][2];
#pragma unroll
    for (int i = 0; i < 4; i++)
#pragma unroll
        for (int g = 0; g < 4; g++) { acc[i][g][0] = 0ull; acc[i][g][1] = 0ull; }

    if constexpr (CIN_X == 1) {
        __syncthreads();
        for (int i = tid; i < 576; i += 256) ((float4*)sW)[i] = ((const float4*)Wx)[i];
        __syncthreads();
        for (int tap = 0; tap < 9; ++tap) {
            const float* a = sX + (tap / 3) * 66 + (tap % 3) + w0;
            unsigned long long aa0 = pack2(a[0]);
            unsigned long long aa1 = pack2(a[1]);
            unsigned long long aa2 = pack2(a[2]);
            unsigned long long aa3 = pack2(a[3]);
            const float* brow = sW + tap * 256 + n0;
#pragma unroll
            for (int g = 0; g < 4; ++g) {
                ulonglong2 bb = *(const ulonglong2*)(brow + g * 64);
                fma2(acc[0][g][0], aa0, bb.x); fma2(acc[0][g][1], aa0, bb.y);
                fma2(acc[1][g][0], aa1, bb.x); fma2(acc[1][g][1], aa1, bb.y);
                fma2(acc[2][g][0], aa2, bb.x); fma2(acc[2][g][1], aa2, bb.y);
                fma2(acc[3][g][0], aa3, bb.x); fma2(acc[3][g][1], aa3, bb.y);
            }
        }
    } else {
        conv_part64(acc, sX, Wx, sW, tid, w0, n0);
    }
    if constexpr (HAS_PREV) {
        conv_part64(acc, sH, Wh, sW, tid, w0, n0);
    }

    // ---------- fused epilogue: bias + activations + state update ----------
    float bg[4][4];
#pragma unroll
    for (int g = 0; g < 4; ++g) {
        float4 t = *(const float4*)(bias + g * 64 + n0);
        bg[g][0] = t.x; bg[g][1] = t.y; bg[g][2] = t.z; bg[g][3] = t.w;
    }
    const long long obase = ((long long)bh * 64 + w0) * 64 + n0;
#pragma unroll
    for (int i = 0; i < 4; i++) {
        long long off = obase + (long long)i * 64;
        float cp[4] = {0.f, 0.f, 0.f, 0.f};
        if constexpr (HAS_PREV) {
            float4 t = *(const float4*)&cbuf[off];
            cp[0] = t.x; cp[1] = t.y; cp[2] = t.z; cp[3] = t.w;
        }
        float gv[4][4];
#pragma unroll
        for (int g = 0; g < 4; ++g) {
            float2 p0 = unpk(acc[i][g][0]);
            float2 p1 = unpk(acc[i][g][1]);
            gv[g][0] = p0.x + bg[g][0];
            gv[g][1] = p0.y + bg[g][1];
            gv[g][2] = p1.x + bg[g][2];
            gv[g][3] = p1.y + bg[g][3];
        }
        float cn[4], hn[4];
#pragma unroll
        for (int j = 0; j < 4; j++) {
            float iv = hsig(gv[0][j]);
            float fv = hsig(gv[1][j]);
            float gg = tanhf(gv[2][j]);
            float ov = hsig(gv[3][j]);
            float c = fv * cp[j] + iv * gg;
            cn[j] = c;
            hn[j] = ov * tanhf(c);
        }
        *(float4*)&cbuf[off] = make_float4(cn[0], cn[1], cn[2], cn[3]);
        *(float4*)&hout[off] = make_float4(hn[0], hn[1], hn[2], hn[3]);
    }
}

extern "C" void kernel_launch(void* const* d_in, const int* in_sizes, int n_in,
                              void* d_out, int out_size)
{
    const float* x   = (const float*)d_in[0];  // [8,10,64,64,1]
    const float* Wx0 = (const float*)d_in[1];  // [3,3,1,256]
    const float* Wh0 = (const float*)d_in[2];  // [3,3,64,256]
    const float* b0  = (const float*)d_in[3];  // [256]
    const float* Wx1 = (const float*)d_in[4];  // [3,3,64,256]
    const float* Wh1 = (const float*)d_in[5];  // [3,3,64,256]
    const float* b1  = (const float*)d_in[6];  // [256]
    float* out = (float*)d_out;                // [2,2,8,64,64,64]

    float *hist0, *hist1, *c0, *c1;
    cudaGetSymbolAddress((void**)&hist0, g_hist0);
    cudaGetSymbolAddress((void**)&hist1, g_hist1);
    cudaGetSymbolAddress((void**)&c0, g_c0);
    cudaGetSymbolAddress((void**)&c1, g_c1);

    const int SM_1N  = (200 + 4096) * 4;
    const int SM_1P  = (200 + 12672 + 4096) * 4;
    const int SM_64N = (12672 + 4096) * 4;
    const int SM_64P = (2 * 12672 + 4096) * 4;
    cudaFuncSetAttribute(step_kernel<1, false>,  cudaFuncAttributeMaxDynamicSharedMemorySize, SM_1N);
    cudaFuncSetAttribute(step_kernel<1, true>,   cudaFuncAttributeMaxDynamicSharedMemorySize, SM_1P);
    cudaFuncSetAttribute(step_kernel<64, false>, cudaFuncAttributeMaxDynamicSharedMemorySize, SM_64N);
    cudaFuncSetAttribute(step_kernel<64, true>,  cudaFuncAttributeMaxDynamicSharedMemorySize, SM_64P);

    dim3 grid(512), block(256);

    // Layer 0: x frame t at x + t*4096, batch stride T*H*W = 40960
    step_kernel<1, false><<<grid, block, SM_1N>>>(x, 40960LL, nullptr,
                                                  Wx0, Wh0, b0, c0, hist0);
    for (int t = 1; t < 10; ++t)
        step_kernel<1, true><<<grid, block, SM_1P>>>(x + (size_t)t * 4096, 40960LL,
                                                     hist0 + (size_t)(t - 1) * FR,
                                                     Wx0, Wh0, b0, c0,
                                                     hist0 + (size_t)t * FR);

    // Layer 1: input is hist0 frames, batch stride H*W*F = 262144
    step_kernel<64, false><<<grid, block, SM_64N>>>(hist0, 262144LL, nullptr,
                                                    Wx1, Wh1, b1, c1, hist1);
    for (int t = 1; t < 10; ++t)
        step_kernel<64, true><<<grid, block, SM_64P>>>(hist0 + (size_t)t * FR, 262144LL,
                                                       hist1 + (size_t)(t - 1) * FR,
                                                       Wx1, Wh1, b1, c1,
                                                       hist1 + (size_t)t * FR);

    // Pack output: [ [h0,c0], [h1,c1] ]
    cudaMemcpyAsync(out,                 hist0 + 9ull * FR, (size_t)FR * 4, cudaMemcpyDeviceToDevice);
    cudaMemcpyAsync(out + (size_t)FR,    c0,                (size_t)FR * 4, cudaMemcpyDeviceToDevice);
    cudaMemcpyAsync(out + 2ull * FR,     hist1 + 9ull * FR, (size_t)FR * 4, cudaMemcpyDeviceToDevice);
    cudaMemcpyAsync(out + 3ull * FR,     c1,                (size_t)FR * 4, cudaMemcpyDeviceToDevice);
}